// round 13
// baseline (speedup 1.0000x reference)
#include <cuda_runtime.h>
#include <cuda_bf16.h>
#include <cuda_fp16.h>
#include <math.h>
#include <stdint.h>

#define NFEAT 256
#define NHID  128
#define NCLASS 16
#define MAXN 100000
#define MAXE 3200000

// ---------------- device scratch (static allocation, allowed) ----------------
__device__ __half g_H0[(size_t)MAXN * NHID];   // x @ W1, fp16 (halves SPMM1 gather)
__device__ __half g_H2h[(size_t)MAXN * NCLASS];// spmm1->relu->@W2, fp16 (halves SPMM2 gather)
__device__ float g_W2t[NCLASS * NHID];         // W2 transposed [16][128]
__device__ __nv_bfloat16 g_Bhi[NHID * NFEAT];  // W1^T split-high [n][k]
__device__ __nv_bfloat16 g_Blo[NHID * NFEAT];  // W1^T split-low  [n][k]
__device__ int   g_offs[MAXN + 1];
__device__ int   g_cursor[MAXN];
__device__ int2  g_epair[MAXE];                // (src, weight-bits), CSR order
__device__ int   g_bsum[512];
__device__ int   g_bexc[512];

// ---------------- mma.sync m16n8k16 bf16 (sm_80+ baseline, sm_103-safe) -----
__device__ __forceinline__ void mma16816(float* c, const uint32_t* a, const uint32_t* b) {
    asm volatile("mma.sync.aligned.m16n8k16.row.col.f32.bf16.bf16.f32 "
                 "{%0,%1,%2,%3}, {%4,%5,%6,%7}, {%8,%9}, {%0,%1,%2,%3};"
                 : "+f"(c[0]), "+f"(c[1]), "+f"(c[2]), "+f"(c[3])
                 : "r"(a[0]), "r"(a[1]), "r"(a[2]), "r"(a[3]),
                   "r"(b[0]), "r"(b[1]));
}

#define CP_ASYNC_16(smem_u32, gptr) \
    asm volatile("cp.async.cg.shared.global [%0], [%1], 16;" \
                 :: "r"(smem_u32), "l"(gptr) : "memory")
#define CP_ASYNC_COMMIT() asm volatile("cp.async.commit_group;" ::: "memory")
#define CP_ASYNC_WAIT0()  asm volatile("cp.async.wait_group 0;" ::: "memory")

// ---------------- scan helper ----------------
__device__ __forceinline__ int block_incl_scan(int v, int* swarp, int nwarps) {
    int lane = threadIdx.x & 31, wid = threadIdx.x >> 5;
    #pragma unroll
    for (int o = 1; o < 32; o <<= 1) {
        int n = __shfl_up_sync(0xffffffffu, v, o);
        if (lane >= o) v += n;
    }
    if (lane == 31) swarp[wid] = v;
    __syncthreads();
    if (wid == 0) {
        int s = (lane < nwarps) ? swarp[lane] : 0;
        #pragma unroll
        for (int o = 1; o < 32; o <<= 1) {
            int n = __shfl_up_sync(0xffffffffu, s, o);
            if (lane >= o) s += n;
        }
        swarp[lane] = s;
    }
    __syncthreads();
    if (wid > 0) v += swarp[wid - 1];
    return v;
}

// ---------------- prep: zero offs + split-transpose W1 + transpose W2 --------
__global__ void zero_prep_kernel(const float* __restrict__ W1, const float* __restrict__ W2, int L) {
    int b = blockIdx.x;
    if (b < NHID) {
        int n = b, k = threadIdx.x;      // 256 threads = 256 k
        float v = W1[(size_t)k * NHID + n];
        __nv_bfloat16 hi = __float2bfloat16(v);
        __nv_bfloat16 lo = __float2bfloat16(v - __bfloat162float(hi));
        g_Bhi[n * NFEAT + k] = hi;
        g_Blo[n * NFEAT + k] = lo;
    }
    if (b == gridDim.x - 1) {
        for (int i = threadIdx.x; i < NHID * NCLASS; i += blockDim.x) {
            int k = i >> 4, c = i & 15;
            g_W2t[c * NHID + k] = W2[i];
        }
    }
    int i = b * blockDim.x + threadIdx.x;
    if (i < L) g_offs[i] = 0;
}

// ---------------- CSR construction ----------------
__global__ void degree_kernel(const int* __restrict__ dst, int E) {
    int e = blockIdx.x * blockDim.x + threadIdx.x;
    if (e < E) atomicAdd(&g_offs[dst[e] + 1], 1);
}
__global__ void scan_block_sums(int L) {
    __shared__ int sw[32];
    int i = blockIdx.x * blockDim.x + threadIdx.x;
    int v = (i < L) ? g_offs[i] : 0;
    int incl = block_incl_scan(v, sw, blockDim.x >> 5);
    if (threadIdx.x == blockDim.x - 1) g_bsum[blockIdx.x] = incl;
}
__global__ void scan_partials(int NB) {
    __shared__ int sw[32];
    int t = threadIdx.x;
    int v = (t < NB) ? g_bsum[t] : 0;
    int incl = block_incl_scan(v, sw, blockDim.x >> 5);
    g_bexc[t] = incl - v;
}
__global__ void scan_apply(int L) {
    __shared__ int sw[32];
    int i = blockIdx.x * blockDim.x + threadIdx.x;
    int v = (i < L) ? g_offs[i] : 0;
    int incl = block_incl_scan(v, sw, blockDim.x >> 5);
    if (i < L) {
        int val = incl + g_bexc[blockIdx.x];
        g_offs[i] = val;
        if (i < L - 1) g_cursor[i] = val;
    }
}
__global__ void fill_csr(const int* __restrict__ src, const int* __restrict__ dst,
                         const float* __restrict__ w, int E) {
    int e = blockIdx.x * blockDim.x + threadIdx.x;
    if (e >= E) return;
    int d = dst[e];
    int p = atomicAdd(&g_cursor[d], 1);
    g_epair[p] = make_int2(src[e], __float_as_int(w[e]));
}

// ---------------- GEMM1: H0 = x @ W1, bf16-split mma.sync, 64x128 tile -------
// 64 rows x 128 cols per CTA, 8 warps (2m x 4n), warp = 32x32 = 2x4 m16n8k16
// tiles -> only 32 accumulator regs. __launch_bounds__(256, 3): 85-reg cap,
// ~70 natural -> no spill, 3 CTAs/SM for cross-CTA latency hiding.
// A read once (tile spans full NHID); B re-read per row-block but L2-hot.
#define ASTR 40

__global__ void __launch_bounds__(256, 3) gemm1_mma_kernel(const float* __restrict__ X, int N) {
    __shared__ __nv_bfloat16 sAh[64][ASTR];
    __shared__ __nv_bfloat16 sAl[64][ASTR];
    __shared__ __nv_bfloat16 sBh[128][ASTR];
    __shared__ __nv_bfloat16 sBl[128][ASTR];

    const int tid = threadIdx.x, lane = tid & 31, wid = tid >> 5;
    const int wm = wid >> 2, wn = wid & 3;          // warp grid 2x4
    const int r = lane >> 2, cc = (lane & 3) * 2;   // groupID / in-group k-pair
    const int bRow = blockIdx.x * 64;

    float acc[2][4][4];
    #pragma unroll
    for (int mt = 0; mt < 2; mt++)
        #pragma unroll
        for (int nt = 0; nt < 4; nt++)
            #pragma unroll
            for (int q = 0; q < 4; q++) acc[mt][nt][q] = 0.f;

    for (int kc = 0; kc < NFEAT; kc += 32) {
        // ---- B chunk via cp.async: 128 n x 32 k hi+lo (L2-hot) ----
        {
            int n = tid >> 1, kq = tid & 1;
            #pragma unroll
            for (int j = 0; j < 2; j++) {
                int kqq = kq + j * 2;
                uint32_t dh = (uint32_t)__cvta_generic_to_shared(&sBh[n][kqq * 8]);
                uint32_t dl = (uint32_t)__cvta_generic_to_shared(&sBl[n][kqq * 8]);
                CP_ASYNC_16(dh, &g_Bhi[n * NFEAT + kc + kqq * 8]);
                CP_ASYNC_16(dl, &g_Blo[n * NFEAT + kc + kqq * 8]);
            }
            CP_ASYNC_COMMIT();
        }
        // ---- stage A chunk: 64 rows x 32 k, f32 -> bf16 hi/lo ----
        #pragma unroll
        for (int i = 0; i < 2; i++) {
            int slot = i * 256 + tid;           // 512 float4 slots
            int row = slot >> 3, q = slot & 7;  // 8 float4 per row
            float4 v = make_float4(0.f, 0.f, 0.f, 0.f);
            if (bRow + row < N)
                v = *reinterpret_cast<const float4*>(&X[(size_t)(bRow + row) * NFEAT + kc + q * 4]);
            __nv_bfloat16 hx = __float2bfloat16(v.x), hy = __float2bfloat16(v.y);
            __nv_bfloat16 hz = __float2bfloat16(v.z), hw = __float2bfloat16(v.w);
            sAh[row][q * 4 + 0] = hx; sAh[row][q * 4 + 1] = hy;
            sAh[row][q * 4 + 2] = hz; sAh[row][q * 4 + 3] = hw;
            sAl[row][q * 4 + 0] = __float2bfloat16(v.x - __bfloat162float(hx));
            sAl[row][q * 4 + 1] = __float2bfloat16(v.y - __bfloat162float(hy));
            sAl[row][q * 4 + 2] = __float2bfloat16(v.z - __bfloat162float(hz));
            sAl[row][q * 4 + 3] = __float2bfloat16(v.w - __bfloat162float(hw));
        }
        CP_ASYNC_WAIT0();
        __syncthreads();

        #pragma unroll
        for (int ks = 0; ks < 32; ks += 16) {
            uint32_t Ah[2][4], Al[2][4];
            #pragma unroll
            for (int mt = 0; mt < 2; mt++) {
                int row0 = wm * 32 + mt * 16 + r;
                Ah[mt][0] = *reinterpret_cast<const uint32_t*>(&sAh[row0][ks + cc]);
                Ah[mt][1] = *reinterpret_cast<const uint32_t*>(&sAh[row0 + 8][ks + cc]);
                Ah[mt][2] = *reinterpret_cast<const uint32_t*>(&sAh[row0][ks + cc + 8]);
                Ah[mt][3] = *reinterpret_cast<const uint32_t*>(&sAh[row0 + 8][ks + cc + 8]);
                Al[mt][0] = *reinterpret_cast<const uint32_t*>(&sAl[row0][ks + cc]);
                Al[mt][1] = *reinterpret_cast<const uint32_t*>(&sAl[row0 + 8][ks + cc]);
                Al[mt][2] = *reinterpret_cast<const uint32_t*>(&sAl[row0][ks + cc + 8]);
                Al[mt][3] = *reinterpret_cast<const uint32_t*>(&sAl[row0 + 8][ks + cc + 8]);
            }
            #pragma unroll
            for (int nt = 0; nt < 4; nt++) {
                int n0 = wn * 32 + nt * 8 + r;
                uint32_t Bh[2], Bl[2];
                Bh[0] = *reinterpret_cast<const uint32_t*>(&sBh[n0][ks + cc]);
                Bh[1] = *reinterpret_cast<const uint32_t*>(&sBh[n0][ks + cc + 8]);
                Bl[0] = *reinterpret_cast<const uint32_t*>(&sBl[n0][ks + cc]);
                Bl[1] = *reinterpret_cast<const uint32_t*>(&sBl[n0][ks + cc + 8]);
                #pragma unroll
                for (int mt = 0; mt < 2; mt++) {
                    mma16816(acc[mt][nt], Ah[mt], Bh);
                    mma16816(acc[mt][nt], Ah[mt], Bl);
                    mma16816(acc[mt][nt], Al[mt], Bh);
                }
            }
        }
        __syncthreads();
    }

    // ---- epilogue: fp16 H0 ----
    #pragma unroll
    for (int mt = 0; mt < 2; mt++) {
        int row0 = bRow + wm * 32 + mt * 16 + r;
        #pragma unroll
        for (int nt = 0; nt < 4; nt++) {
            int col = wn * 32 + nt * 8 + cc;
            if (row0 < N)
                *reinterpret_cast<__half2*>(&g_H0[(size_t)row0 * NHID + col]) =
                    __floats2half2_rn(acc[mt][nt][0], acc[mt][nt][1]);
            if (row0 + 8 < N)
                *reinterpret_cast<__half2*>(&g_H0[(size_t)(row0 + 8) * NHID + col]) =
                    __floats2half2_rn(acc[mt][nt][2], acc[mt][nt][3]);
        }
    }
}

// ---------------- Fused SPMM1 + bias + relu + GEMM2 (unroll 4 for MLP) -------
__device__ __forceinline__ void fma_h4(float4& acc, float w, uint2 u) {
    float2 f0 = __half22float2(*reinterpret_cast<__half2*>(&u.x));
    float2 f1 = __half22float2(*reinterpret_cast<__half2*>(&u.y));
    acc.x = fmaf(w, f0.x, acc.x); acc.y = fmaf(w, f0.y, acc.y);
    acc.z = fmaf(w, f1.x, acc.z); acc.w = fmaf(w, f1.y, acc.w);
}

__global__ void spmm1_gemm2_kernel(const float* __restrict__ b1, int N) {
    int warp = (blockIdx.x * blockDim.x + threadIdx.x) >> 5;
    int lane = threadIdx.x & 31;
    if (warp >= N) return;
    int beg = g_offs[warp], end = g_offs[warp + 1];
    const uint2* H0v = reinterpret_cast<const uint2*>(g_H0);
    float4 acc = make_float4(0.f, 0.f, 0.f, 0.f);
    int e = beg;
    for (; e + 3 < end; e += 4) {
        int2 p0 = g_epair[e],     p1 = g_epair[e + 1];
        int2 p2 = g_epair[e + 2], p3 = g_epair[e + 3];
        uint2 v0 = H0v[(size_t)p0.x * 32 + lane];
        uint2 v1 = H0v[(size_t)p1.x * 32 + lane];
        uint2 v2 = H0v[(size_t)p2.x * 32 + lane];
        uint2 v3 = H0v[(size_t)p3.x * 32 + lane];
        fma_h4(acc, __int_as_float(p0.y), v0);
        fma_h4(acc, __int_as_float(p1.y), v1);
        fma_h4(acc, __int_as_float(p2.y), v2);
        fma_h4(acc, __int_as_float(p3.y), v3);
    }
    for (; e < end; e++) {
        int2 p0 = g_epair[e];
        uint2 v0 = H0v[(size_t)p0.x * 32 + lane];
        fma_h4(acc, __int_as_float(p0.y), v0);
    }
    float4 bb = __ldg(&reinterpret_cast<const float4*>(b1)[lane]);
    float4 h;
    h.x = fmaxf(acc.x + bb.x, 0.f);
    h.y = fmaxf(acc.y + bb.y, 0.f);
    h.z = fmaxf(acc.z + bb.z, 0.f);
    h.w = fmaxf(acc.w + bb.w, 0.f);

    const float4* W2t4 = reinterpret_cast<const float4*>(g_W2t);
    float p[16];
    #pragma unroll
    for (int c = 0; c < 16; c++) {
        float4 wv = __ldg(&W2t4[c * 32 + lane]);
        float t = h.x * wv.x;
        t = fmaf(h.y, wv.y, t);
        t = fmaf(h.z, wv.z, t);
        t = fmaf(h.w, wv.w, t);
        p[c] = t;
    }
    {   bool hi = (lane & 1);
        #pragma unroll
        for (int k = 0; k < 8; k++) {
            float send = hi ? p[k] : p[k + 8];
            float recv = __shfl_xor_sync(0xffffffffu, send, 1);
            p[k] = (hi ? p[k + 8] : p[k]) + recv;
        }
    }
    {   bool hi = (lane & 2);
        #pragma unroll
        for (int k = 0; k < 4; k++) {
            float send = hi ? p[k] : p[k + 4];
            float recv = __shfl_xor_sync(0xffffffffu, send, 2);
            p[k] = (hi ? p[k + 4] : p[k]) + recv;
        }
    }
    {   bool hi = (lane & 4);
        #pragma unroll
        for (int k = 0; k < 2; k++) {
            float send = hi ? p[k] : p[k + 2];
            float recv = __shfl_xor_sync(0xffffffffu, send, 4);
            p[k] = (hi ? p[k + 2] : p[k]) + recv;
        }
    }
    {   bool hi = (lane & 8);
        float send = hi ? p[0] : p[1];
        float recv = __shfl_xor_sync(0xffffffffu, send, 8);
        p[0] = (hi ? p[1] : p[0]) + recv;
    }
    p[0] += __shfl_xor_sync(0xffffffffu, p[0], 16);
    int c = ((lane & 1) << 3) | ((lane & 2) << 1) | ((lane & 4) >> 1) | ((lane & 8) >> 3);
    if (lane < 16) g_H2h[(size_t)warp * NCLASS + c] = __float2half(p[0]);
}

// ---------------- SPMM2 + bias + log_softmax (fp16 H2, 8 lanes/row) ----------
__global__ void spmm2_kernel(const float* __restrict__ b2, float* __restrict__ out, int N) {
    int gwarp = (blockIdx.x * blockDim.x + threadIdx.x) >> 5;
    int lane = threadIdx.x & 31;
    int grp = lane >> 3, sub = lane & 7;   // row-group / class-pair index
    int row = gwarp * 4 + grp;
    float a0 = 0.f, a1 = 0.f;
    const uint32_t* H2v = reinterpret_cast<const uint32_t*>(g_H2h);  // 8 uints/row
    if (row < N) {
        int beg = g_offs[row], end = g_offs[row + 1];
        int e = beg;
        for (; e + 1 < end; e += 2) {
            int2 p0 = g_epair[e], p1 = g_epair[e + 1];
            uint32_t u0 = __ldg(&H2v[(size_t)p0.x * 8 + sub]);
            uint32_t u1 = __ldg(&H2v[(size_t)p1.x * 8 + sub]);
            float w0 = __int_as_float(p0.y), w1 = __int_as_float(p1.y);
            float2 f0 = __half22float2(*reinterpret_cast<__half2*>(&u0));
            float2 f1 = __half22float2(*reinterpret_cast<__half2*>(&u1));
            a0 = fmaf(w0, f0.x, a0); a1 = fmaf(w0, f0.y, a1);
            a0 = fmaf(w1, f1.x, a0); a1 = fmaf(w1, f1.y, a1);
        }
        if (e < end) {
            int2 p0 = g_epair[e];
            uint32_t u0 = __ldg(&H2v[(size_t)p0.x * 8 + sub]);
            float2 f0 = __half22float2(*reinterpret_cast<__half2*>(&u0));
            float w0 = __int_as_float(p0.y);
            a0 = fmaf(w0, f0.x, a0); a1 = fmaf(w0, f0.y, a1);
        }
    }
    float2 bb = __ldg(&reinterpret_cast<const float2*>(b2)[sub]);
    a0 += bb.x; a1 += bb.y;
    float m = fmaxf(a0, a1);
    #pragma unroll
    for (int o = 4; o > 0; o >>= 1) m = fmaxf(m, __shfl_xor_sync(0xffffffffu, m, o, 8));
    float s = expf(a0 - m) + expf(a1 - m);
    #pragma unroll
    for (int o = 4; o > 0; o >>= 1) s += __shfl_xor_sync(0xffffffffu, s, o, 8);
    float ls = logf(s);
    if (row < N)
        reinterpret_cast<float2*>(out)[(size_t)row * 8 + sub] =
            make_float2(a0 - m - ls, a1 - m - ls);
}

// ---------------- launch: fork/join — CSR build on side stream ∥ GEMM1 -------
extern "C" void kernel_launch(void* const* d_in, const int* in_sizes, int n_in,
                              void* d_out, int out_size) {
    const float* x   = (const float*)d_in[0];
    const float* W1  = (const float*)d_in[1];
    const float* b1  = (const float*)d_in[2];
    const float* W2  = (const float*)d_in[3];
    const float* b2  = (const float*)d_in[4];
    const float* ew  = (const float*)d_in[5];
    const int*   src = (const int*)d_in[6];
    const int*   dst = (const int*)d_in[7];
    float* out = (float*)d_out;

    const int N = in_sizes[0] / NFEAT;
    const int E = in_sizes[5];
    const int L = N + 1;
    const int NB = (L + 255) / 256;   // <= 512

    // one-time host-side resources (no device memory involved)
    static cudaStream_t s2 = nullptr;
    static cudaEvent_t ev_fork = nullptr, ev_join = nullptr;
    if (s2 == nullptr) {
        cudaStreamCreateWithFlags(&s2, cudaStreamNonBlocking);
        cudaEventCreateWithFlags(&ev_fork, cudaEventDisableTiming);
        cudaEventCreateWithFlags(&ev_join, cudaEventDisableTiming);
    }

    // common prep on main stream
    zero_prep_kernel<<<NB, 256>>>(W1, W2, L);                      // 1

    // fork: CSR chain on s2, concurrent with gemm1 on main stream
    cudaEventRecord(ev_fork, 0);
    cudaStreamWaitEvent(s2, ev_fork, 0);

    degree_kernel<<<(E + 255) / 256, 256, 0, s2>>>(dst, E);        // 2
    scan_block_sums<<<NB, 256, 0, s2>>>(L);                        // 3
    gemm1_mma_kernel<<<(N + 63) / 64, 256>>>(x, N);                // 4 <- profiled
    scan_partials<<<1, 512, 0, s2>>>(NB);                          // 5
    scan_apply<<<NB, 256, 0, s2>>>(L);                             // 6
    fill_csr<<<(E + 255) / 256, 256, 0, s2>>>(src, dst, ew, E);    // 7
    cudaEventRecord(ev_join, s2);

    // join: spmm needs both CSR (s2) and H0 (main)
    cudaStreamWaitEvent(0, ev_join, 0);
    spmm1_gemm2_kernel<<<(N + 7) / 8, 256>>>(b1, N);               // 8
    spmm2_kernel<<<(N + 31) / 32, 256>>>(b2, out, N);              // 9
}

// round 14
// speedup vs baseline: 1.3485x; 1.3485x over previous
#include <cuda_runtime.h>
#include <cuda_bf16.h>
#include <cuda_fp16.h>
#include <math.h>
#include <stdint.h>

#define NFEAT 256
#define NHID  128
#define NCLASS 16
#define MAXN 100000
#define MAXE 3200000

// ---------------- device scratch (static allocation, allowed) ----------------
__device__ __half g_H0[(size_t)MAXN * NHID];   // x @ W1, fp16 (halves SPMM1 gather)
__device__ __half g_H2h[(size_t)MAXN * NCLASS];// spmm1->relu->@W2, fp16 (halves SPMM2 gather)
__device__ float g_W2t[NCLASS * NHID];         // W2 transposed [16][128]
__device__ __nv_bfloat16 g_Bhi[NHID * NFEAT];  // W1^T split-high [n][k]
__device__ __nv_bfloat16 g_Blo[NHID * NFEAT];  // W1^T split-low  [n][k]
__device__ int   g_offs[MAXN + 1];
__device__ int   g_cursor[MAXN];
__device__ int2  g_epair[MAXE];                // (src, weight-bits), CSR order
__device__ int   g_bsum[512];
__device__ int   g_bexc[512];

// ---------------- mma.sync m16n8k16 bf16 (sm_80+ baseline, sm_103-safe) -----
__device__ __forceinline__ void mma16816(float* c, const uint32_t* a, const uint32_t* b) {
    asm volatile("mma.sync.aligned.m16n8k16.row.col.f32.bf16.bf16.f32 "
                 "{%0,%1,%2,%3}, {%4,%5,%6,%7}, {%8,%9}, {%0,%1,%2,%3};"
                 : "+f"(c[0]), "+f"(c[1]), "+f"(c[2]), "+f"(c[3])
                 : "r"(a[0]), "r"(a[1]), "r"(a[2]), "r"(a[3]),
                   "r"(b[0]), "r"(b[1]));
}

#define CP_ASYNC_16(smem_u32, gptr) \
    asm volatile("cp.async.cg.shared.global [%0], [%1], 16;" \
                 :: "r"(smem_u32), "l"(gptr) : "memory")
#define CP_ASYNC_COMMIT() asm volatile("cp.async.commit_group;" ::: "memory")
#define CP_ASYNC_WAIT0()  asm volatile("cp.async.wait_group 0;" ::: "memory")

// ---------------- scan helper ----------------
__device__ __forceinline__ int block_incl_scan(int v, int* swarp, int nwarps) {
    int lane = threadIdx.x & 31, wid = threadIdx.x >> 5;
    #pragma unroll
    for (int o = 1; o < 32; o <<= 1) {
        int n = __shfl_up_sync(0xffffffffu, v, o);
        if (lane >= o) v += n;
    }
    if (lane == 31) swarp[wid] = v;
    __syncthreads();
    if (wid == 0) {
        int s = (lane < nwarps) ? swarp[lane] : 0;
        #pragma unroll
        for (int o = 1; o < 32; o <<= 1) {
            int n = __shfl_up_sync(0xffffffffu, s, o);
            if (lane >= o) s += n;
        }
        swarp[lane] = s;
    }
    __syncthreads();
    if (wid > 0) v += swarp[wid - 1];
    return v;
}

// ---------------- prep: zero offs + split-transpose W1 + transpose W2 --------
__global__ void zero_prep_kernel(const float* __restrict__ W1, const float* __restrict__ W2, int L) {
    int b = blockIdx.x;
    if (b < NHID) {
        int n = b, k = threadIdx.x;      // 256 threads = 256 k
        float v = W1[(size_t)k * NHID + n];
        __nv_bfloat16 hi = __float2bfloat16(v);
        __nv_bfloat16 lo = __float2bfloat16(v - __bfloat162float(hi));
        g_Bhi[n * NFEAT + k] = hi;
        g_Blo[n * NFEAT + k] = lo;
    }
    if (b == gridDim.x - 1) {
        for (int i = threadIdx.x; i < NHID * NCLASS; i += blockDim.x) {
            int k = i >> 4, c = i & 15;
            g_W2t[c * NHID + k] = W2[i];
        }
    }
    int i = b * blockDim.x + threadIdx.x;
    if (i < L) g_offs[i] = 0;
}

// ---------------- CSR construction ----------------
__global__ void degree_kernel(const int* __restrict__ dst, int E) {
    int e = blockIdx.x * blockDim.x + threadIdx.x;
    if (e < E) atomicAdd(&g_offs[dst[e] + 1], 1);
}
__global__ void scan_block_sums(int L) {
    __shared__ int sw[32];
    int i = blockIdx.x * blockDim.x + threadIdx.x;
    int v = (i < L) ? g_offs[i] : 0;
    int incl = block_incl_scan(v, sw, blockDim.x >> 5);
    if (threadIdx.x == blockDim.x - 1) g_bsum[blockIdx.x] = incl;
}
__global__ void scan_partials(int NB) {
    __shared__ int sw[32];
    int t = threadIdx.x;
    int v = (t < NB) ? g_bsum[t] : 0;
    int incl = block_incl_scan(v, sw, blockDim.x >> 5);
    g_bexc[t] = incl - v;
}
__global__ void scan_apply(int L) {
    __shared__ int sw[32];
    int i = blockIdx.x * blockDim.x + threadIdx.x;
    int v = (i < L) ? g_offs[i] : 0;
    int incl = block_incl_scan(v, sw, blockDim.x >> 5);
    if (i < L) {
        int val = incl + g_bexc[blockIdx.x];
        g_offs[i] = val;
        if (i < L - 1) g_cursor[i] = val;
    }
}
__global__ void fill_csr(const int* __restrict__ src, const int* __restrict__ dst,
                         const float* __restrict__ w, int E) {
    int e = blockIdx.x * blockDim.x + threadIdx.x;
    if (e >= E) return;
    int d = dst[e];
    int p = atomicAdd(&g_cursor[d], 1);
    g_epair[p] = make_int2(src[e], __float_as_int(w[e]));
}

// ---------------- GEMM1: H0 = bf16(x) @ W1, 2-term mma.sync ------------------
// 128x128 tile per CTA (R12 geometry). 2-term split: Ah*(Bh+Bl) — full-precision
// weights, only x carries bf16 rounding (x-err attenuates ~7x through the net).
// MMAs/chunk 48->32, A staging halved, smem 41->31KB.
#define ASTR 40

__global__ void __launch_bounds__(256, 2) gemm1_mma_kernel(const float* __restrict__ X, int N) {
    __shared__ __nv_bfloat16 sAh[128][ASTR];
    __shared__ __nv_bfloat16 sBh[128][ASTR];
    __shared__ __nv_bfloat16 sBl[128][ASTR];

    const int tid = threadIdx.x, lane = tid & 31, wid = tid >> 5;
    const int wm = wid >> 1, wn = wid & 1;          // warp grid 4x2
    const int r = lane >> 2, cc = (lane & 3) * 2;   // groupID / in-group k-pair
    const int bRow = blockIdx.x * 128;

    float acc[2][8][4];
    #pragma unroll
    for (int mt = 0; mt < 2; mt++)
        #pragma unroll
        for (int nt = 0; nt < 8; nt++)
            #pragma unroll
            for (int q = 0; q < 4; q++) acc[mt][nt][q] = 0.f;

    for (int kc = 0; kc < NFEAT; kc += 32) {
        // ---- B chunk via cp.async: hi+lo (overlaps A convert work) ----
        {
            int n = tid >> 1, kq = tid & 1;
            #pragma unroll
            for (int j = 0; j < 2; j++) {
                int kqq = kq + j * 2;
                uint32_t dh = (uint32_t)__cvta_generic_to_shared(&sBh[n][kqq * 8]);
                uint32_t dl = (uint32_t)__cvta_generic_to_shared(&sBl[n][kqq * 8]);
                CP_ASYNC_16(dh, &g_Bhi[n * NFEAT + kc + kqq * 8]);
                CP_ASYNC_16(dl, &g_Blo[n * NFEAT + kc + kqq * 8]);
            }
            CP_ASYNC_COMMIT();
        }
        // ---- stage A chunk: 128 rows x 32 k, f32 -> bf16 (hi only) ----
        #pragma unroll
        for (int i = 0; i < 4; i++) {
            int slot = i * 256 + tid;
            int row = slot >> 3, q = slot & 7;
            float4 v = make_float4(0.f, 0.f, 0.f, 0.f);
            if (bRow + row < N)
                v = *reinterpret_cast<const float4*>(&X[(size_t)(bRow + row) * NFEAT + kc + q * 4]);
            sAh[row][q * 4 + 0] = __float2bfloat16(v.x);
            sAh[row][q * 4 + 1] = __float2bfloat16(v.y);
            sAh[row][q * 4 + 2] = __float2bfloat16(v.z);
            sAh[row][q * 4 + 3] = __float2bfloat16(v.w);
        }
        CP_ASYNC_WAIT0();
        __syncthreads();

        #pragma unroll
        for (int ks = 0; ks < 32; ks += 16) {
            uint32_t Ah[2][4];
            #pragma unroll
            for (int mt = 0; mt < 2; mt++) {
                int row0 = wm * 32 + mt * 16 + r;
                Ah[mt][0] = *reinterpret_cast<const uint32_t*>(&sAh[row0][ks + cc]);
                Ah[mt][1] = *reinterpret_cast<const uint32_t*>(&sAh[row0 + 8][ks + cc]);
                Ah[mt][2] = *reinterpret_cast<const uint32_t*>(&sAh[row0][ks + cc + 8]);
                Ah[mt][3] = *reinterpret_cast<const uint32_t*>(&sAh[row0 + 8][ks + cc + 8]);
            }
            #pragma unroll
            for (int nt = 0; nt < 8; nt++) {
                int n0 = wn * 64 + nt * 8 + r;
                uint32_t Bh[2], Bl[2];
                Bh[0] = *reinterpret_cast<const uint32_t*>(&sBh[n0][ks + cc]);
                Bh[1] = *reinterpret_cast<const uint32_t*>(&sBh[n0][ks + cc + 8]);
                Bl[0] = *reinterpret_cast<const uint32_t*>(&sBl[n0][ks + cc]);
                Bl[1] = *reinterpret_cast<const uint32_t*>(&sBl[n0][ks + cc + 8]);
                #pragma unroll
                for (int mt = 0; mt < 2; mt++) {
                    mma16816(acc[mt][nt], Ah[mt], Bh);
                    mma16816(acc[mt][nt], Ah[mt], Bl);
                }
            }
        }
        __syncthreads();
    }

    // ---- epilogue: fp16 H0 ----
    #pragma unroll
    for (int mt = 0; mt < 2; mt++) {
        int row0 = bRow + wm * 32 + mt * 16 + r;
        #pragma unroll
        for (int nt = 0; nt < 8; nt++) {
            int col = wn * 64 + nt * 8 + cc;
            if (row0 < N)
                *reinterpret_cast<__half2*>(&g_H0[(size_t)row0 * NHID + col]) =
                    __floats2half2_rn(acc[mt][nt][0], acc[mt][nt][1]);
            if (row0 + 8 < N)
                *reinterpret_cast<__half2*>(&g_H0[(size_t)(row0 + 8) * NHID + col]) =
                    __floats2half2_rn(acc[mt][nt][2], acc[mt][nt][3]);
        }
    }
}

// ---------------- Fused SPMM1 + bias + relu + GEMM2 (unroll 4 for MLP) -------
__device__ __forceinline__ void fma_h4(float4& acc, float w, uint2 u) {
    float2 f0 = __half22float2(*reinterpret_cast<__half2*>(&u.x));
    float2 f1 = __half22float2(*reinterpret_cast<__half2*>(&u.y));
    acc.x = fmaf(w, f0.x, acc.x); acc.y = fmaf(w, f0.y, acc.y);
    acc.z = fmaf(w, f1.x, acc.z); acc.w = fmaf(w, f1.y, acc.w);
}

__global__ void spmm1_gemm2_kernel(const float* __restrict__ b1, int N) {
    int warp = (blockIdx.x * blockDim.x + threadIdx.x) >> 5;
    int lane = threadIdx.x & 31;
    if (warp >= N) return;
    int beg = g_offs[warp], end = g_offs[warp + 1];
    const uint2* H0v = reinterpret_cast<const uint2*>(g_H0);
    float4 acc = make_float4(0.f, 0.f, 0.f, 0.f);
    int e = beg;
    for (; e + 3 < end; e += 4) {
        int2 p0 = g_epair[e],     p1 = g_epair[e + 1];
        int2 p2 = g_epair[e + 2], p3 = g_epair[e + 3];
        uint2 v0 = H0v[(size_t)p0.x * 32 + lane];
        uint2 v1 = H0v[(size_t)p1.x * 32 + lane];
        uint2 v2 = H0v[(size_t)p2.x * 32 + lane];
        uint2 v3 = H0v[(size_t)p3.x * 32 + lane];
        fma_h4(acc, __int_as_float(p0.y), v0);
        fma_h4(acc, __int_as_float(p1.y), v1);
        fma_h4(acc, __int_as_float(p2.y), v2);
        fma_h4(acc, __int_as_float(p3.y), v3);
    }
    for (; e < end; e++) {
        int2 p0 = g_epair[e];
        uint2 v0 = H0v[(size_t)p0.x * 32 + lane];
        fma_h4(acc, __int_as_float(p0.y), v0);
    }
    float4 bb = __ldg(&reinterpret_cast<const float4*>(b1)[lane]);
    float4 h;
    h.x = fmaxf(acc.x + bb.x, 0.f);
    h.y = fmaxf(acc.y + bb.y, 0.f);
    h.z = fmaxf(acc.z + bb.z, 0.f);
    h.w = fmaxf(acc.w + bb.w, 0.f);

    const float4* W2t4 = reinterpret_cast<const float4*>(g_W2t);
    float p[16];
    #pragma unroll
    for (int c = 0; c < 16; c++) {
        float4 wv = __ldg(&W2t4[c * 32 + lane]);
        float t = h.x * wv.x;
        t = fmaf(h.y, wv.y, t);
        t = fmaf(h.z, wv.z, t);
        t = fmaf(h.w, wv.w, t);
        p[c] = t;
    }
    {   bool hi = (lane & 1);
        #pragma unroll
        for (int k = 0; k < 8; k++) {
            float send = hi ? p[k] : p[k + 8];
            float recv = __shfl_xor_sync(0xffffffffu, send, 1);
            p[k] = (hi ? p[k + 8] : p[k]) + recv;
        }
    }
    {   bool hi = (lane & 2);
        #pragma unroll
        for (int k = 0; k < 4; k++) {
            float send = hi ? p[k] : p[k + 4];
            float recv = __shfl_xor_sync(0xffffffffu, send, 2);
            p[k] = (hi ? p[k + 4] : p[k]) + recv;
        }
    }
    {   bool hi = (lane & 4);
        #pragma unroll
        for (int k = 0; k < 2; k++) {
            float send = hi ? p[k] : p[k + 2];
            float recv = __shfl_xor_sync(0xffffffffu, send, 4);
            p[k] = (hi ? p[k + 2] : p[k]) + recv;
        }
    }
    {   bool hi = (lane & 8);
        float send = hi ? p[0] : p[1];
        float recv = __shfl_xor_sync(0xffffffffu, send, 8);
        p[0] = (hi ? p[1] : p[0]) + recv;
    }
    p[0] += __shfl_xor_sync(0xffffffffu, p[0], 16);
    int c = ((lane & 1) << 3) | ((lane & 2) << 1) | ((lane & 4) >> 1) | ((lane & 8) >> 3);
    if (lane < 16) g_H2h[(size_t)warp * NCLASS + c] = __float2half(p[0]);
}

// ---------------- SPMM2 + bias + log_softmax (fp16 H2, 8 lanes/row) ----------
__global__ void spmm2_kernel(const float* __restrict__ b2, float* __restrict__ out, int N) {
    int gwarp = (blockIdx.x * blockDim.x + threadIdx.x) >> 5;
    int lane = threadIdx.x & 31;
    int grp = lane >> 3, sub = lane & 7;   // row-group / class-pair index
    int row = gwarp * 4 + grp;
    float a0 = 0.f, a1 = 0.f;
    const uint32_t* H2v = reinterpret_cast<const uint32_t*>(g_H2h);  // 8 uints/row
    if (row < N) {
        int beg = g_offs[row], end = g_offs[row + 1];
        int e = beg;
        for (; e + 1 < end; e += 2) {
            int2 p0 = g_epair[e], p1 = g_epair[e + 1];
            uint32_t u0 = __ldg(&H2v[(size_t)p0.x * 8 + sub]);
            uint32_t u1 = __ldg(&H2v[(size_t)p1.x * 8 + sub]);
            float w0 = __int_as_float(p0.y), w1 = __int_as_float(p1.y);
            float2 f0 = __half22float2(*reinterpret_cast<__half2*>(&u0));
            float2 f1 = __half22float2(*reinterpret_cast<__half2*>(&u1));
            a0 = fmaf(w0, f0.x, a0); a1 = fmaf(w0, f0.y, a1);
            a0 = fmaf(w1, f1.x, a0); a1 = fmaf(w1, f1.y, a1);
        }
        if (e < end) {
            int2 p0 = g_epair[e];
            uint32_t u0 = __ldg(&H2v[(size_t)p0.x * 8 + sub]);
            float2 f0 = __half22float2(*reinterpret_cast<__half2*>(&u0));
            float w0 = __int_as_float(p0.y);
            a0 = fmaf(w0, f0.x, a0); a1 = fmaf(w0, f0.y, a1);
        }
    }
    float2 bb = __ldg(&reinterpret_cast<const float2*>(b2)[sub]);
    a0 += bb.x; a1 += bb.y;
    float m = fmaxf(a0, a1);
    #pragma unroll
    for (int o = 4; o > 0; o >>= 1) m = fmaxf(m, __shfl_xor_sync(0xffffffffu, m, o, 8));
    float s = expf(a0 - m) + expf(a1 - m);
    #pragma unroll
    for (int o = 4; o > 0; o >>= 1) s += __shfl_xor_sync(0xffffffffu, s, o, 8);
    float ls = logf(s);
    if (row < N)
        reinterpret_cast<float2*>(out)[(size_t)row * 8 + sub] =
            make_float2(a0 - m - ls, a1 - m - ls);
}

// ---------------- launch: fork/join — CSR build on side stream ∥ GEMM1 -------
extern "C" void kernel_launch(void* const* d_in, const int* in_sizes, int n_in,
                              void* d_out, int out_size) {
    const float* x   = (const float*)d_in[0];
    const float* W1  = (const float*)d_in[1];
    const float* b1  = (const float*)d_in[2];
    const float* W2  = (const float*)d_in[3];
    const float* b2  = (const float*)d_in[4];
    const float* ew  = (const float*)d_in[5];
    const int*   src = (const int*)d_in[6];
    const int*   dst = (const int*)d_in[7];
    float* out = (float*)d_out;

    const int N = in_sizes[0] / NFEAT;
    const int E = in_sizes[5];
    const int L = N + 1;
    const int NB = (L + 255) / 256;   // <= 512

    // one-time host-side resources (no device memory involved)
    static cudaStream_t s2 = nullptr;
    static cudaEvent_t ev_fork = nullptr, ev_join = nullptr;
    if (s2 == nullptr) {
        cudaStreamCreateWithFlags(&s2, cudaStreamNonBlocking);
        cudaEventCreateWithFlags(&ev_fork, cudaEventDisableTiming);
        cudaEventCreateWithFlags(&ev_join, cudaEventDisableTiming);
    }

    // common prep on main stream
    zero_prep_kernel<<<NB, 256>>>(W1, W2, L);                      // 1

    // fork: CSR chain on s2, concurrent with gemm1 on main stream
    cudaEventRecord(ev_fork, 0);
    cudaStreamWaitEvent(s2, ev_fork, 0);

    degree_kernel<<<(E + 255) / 256, 256, 0, s2>>>(dst, E);        // 2
    scan_block_sums<<<NB, 256, 0, s2>>>(L);                        // 3
    gemm1_mma_kernel<<<(N + 127) / 128, 256>>>(x, N);              // 4 <- profiled
    scan_partials<<<1, 512, 0, s2>>>(NB);                          // 5
    scan_apply<<<NB, 256, 0, s2>>>(L);                             // 6
    fill_csr<<<(E + 255) / 256, 256, 0, s2>>>(src, dst, ew, E);    // 7
    cudaEventRecord(ev_join, s2);

    // join: spmm needs both CSR (s2) and H0 (main)
    cudaStreamWaitEvent(0, ev_join, 0);
    spmm1_gemm2_kernel<<<(N + 7) / 8, 256>>>(b1, N);               // 8
    spmm2_kernel<<<(N + 31) / 32, 256>>>(b2, out, N);              // 9
}